// round 1
// baseline (speedup 1.0000x reference)
#include <cuda_runtime.h>
#include <cuda_bf16.h>
#include <math.h>
#include <stdint.h>

// Problem dims (fixed)
#define BB   64
#define TT   20
#define FF   2048
#define EE   512
#define GG   1024
#define VV   32000
#define MROWS (BB*TT)   // 1280

// Scratch (device globals; no allocation allowed)
__device__ float d_X [MROWS * EE];        // [t][b][E] time-major input seq
__device__ float d_GI[MROWS * 3 * GG];    // [t][b][3G] precomputed input gates
__device__ float d_HS[MROWS * GG];        // [t][b][G] hidden states
__device__ float d_scale_img[EE];
__device__ float d_scale_fc [VV];

// ---------------------------------------------------------------- helpers
__device__ __forceinline__ unsigned f2tf32(float x) {
    unsigned r; asm("cvt.rna.tf32.f32 %0, %1;" : "=r"(r) : "f"(x)); return r;
}
__device__ __forceinline__ void mma_tf32(float c[4], const unsigned a[4], const unsigned b[2]) {
    asm volatile(
      "mma.sync.aligned.m16n8k8.row.col.f32.tf32.tf32.f32 "
      "{%0,%1,%2,%3},{%4,%5,%6,%7},{%8,%9},{%0,%1,%2,%3};\n"
      : "+f"(c[0]), "+f"(c[1]), "+f"(c[2]), "+f"(c[3])
      : "r"(a[0]), "r"(a[1]), "r"(a[2]), "r"(a[3]), "r"(b[0]), "r"(b[1]));
}
__device__ __forceinline__ void cp16(unsigned dst, const float* src) {
    asm volatile("cp.async.cg.shared.global [%0], [%1], 16;\n" :: "r"(dst), "l"(src));
}
__device__ __forceinline__ void cp_commit() {
    asm volatile("cp.async.commit_group;\n" ::: "memory");
}
template<int N> __device__ __forceinline__ void cp_wait() {
    asm volatile("cp.async.wait_group %0;\n" :: "n"(N) : "memory");
}
__device__ __forceinline__ float sigmoidf_fast(float x) {
    return 1.0f / (1.0f + __expf(-x));
}

// ---------------------------------------------------------------- row-norm scale
// scale[row] = g[row] / ||V[row,:]||
__global__ void rownorm_kernel(const float* __restrict__ V, const float* __restrict__ g,
                               float* __restrict__ scale, int K) {
    int row = blockIdx.x;
    const float4* v = (const float4*)(V + (size_t)row * K);
    float s = 0.f;
    for (int i = threadIdx.x; i < (K >> 2); i += blockDim.x) {
        float4 x = v[i];
        s += x.x*x.x + x.y*x.y + x.z*x.z + x.w*x.w;
    }
    for (int o = 16; o; o >>= 1) s += __shfl_xor_sync(0xffffffffu, s, o);
    __shared__ float red[4];
    int lane = threadIdx.x & 31, warp = threadIdx.x >> 5;
    if (lane == 0) red[warp] = s;
    __syncthreads();
    if (threadIdx.x == 0) {
        float t = red[0] + red[1] + red[2] + red[3];
        scale[row] = g[row] / sqrtf(t);
    }
}

// ---------------------------------------------------------------- embedding gather (t>=1)
__global__ void gather_kernel(const int* __restrict__ ids, const float* __restrict__ emb) {
    int t = blockIdx.x / BB + 1;
    int b = blockIdx.x % BB;
    int id = ids[b * TT + t];
    const float4* src = (const float4*)(emb + (size_t)id * EE);
    float4* dst = (float4*)(d_X + ((size_t)t * BB + b) * EE);
    for (int i = threadIdx.x; i < EE / 4; i += blockDim.x) dst[i] = src[i];
}

// ---------------------------------------------------------------- img embed (t=0 rows of X)
// X[b, e] = dot(features[b,:], img_v[e,:]) * scale_img[e] + img_b[e]
__global__ __launch_bounds__(256) void img_embed_kernel(
    const float* __restrict__ features, const float* __restrict__ V,
    const float* __restrict__ scale, const float* __restrict__ bias) {
    int wg = (blockIdx.x * blockDim.x + threadIdx.x) >> 5;   // 0 .. 64*512-1
    int lane = threadIdx.x & 31;
    int b = wg >> 9, e = wg & 511;
    const float4* f = (const float4*)(features + (size_t)b * FF);
    const float4* w = (const float4*)(V + (size_t)e * FF);
    float s = 0.f;
    for (int i = lane; i < FF / 4; i += 32) {
        float4 x = f[i], y = w[i];
        s += x.x*y.x + x.y*y.y + x.z*y.z + x.w*y.w;
    }
    for (int o = 16; o; o >>= 1) s += __shfl_xor_sync(0xffffffffu, s, o);
    if (lane == 0) d_X[(size_t)b * EE + e] = s * scale[e] + bias[e];
}

// ---------------------------------------------------------------- generic tf32 GEMM
// C[m,n] = (sum_k A[m,k]*B[n,k]) * scale[n] + bias[n]
// BM=64 BN=128 BK=16, 256 threads (8 warps, 2x4), warp tile 32x32.
// remap=1: row m = t*64+b, write to C[(b*TT+t)*N + n]  (FC output transpose)
__global__ __launch_bounds__(256) void gemm_tf32_kernel(
    const float* __restrict__ A, const float* __restrict__ B, float* __restrict__ C,
    const float* __restrict__ scale, const float* __restrict__ bias,
    int M, int N, int K, int remap) {
    __shared__ float sA[2][64][20];
    __shared__ float sB[2][128][20];

    const int tid = threadIdx.x, lane = tid & 31, warp = tid >> 5;
    const int wm = warp >> 2, wn = warp & 3;
    const int m0 = blockIdx.x * 64, n0 = blockIdx.y * 128;

    const int a_row = tid >> 2, a_c4 = (tid & 3) * 4;
    const float* gA  = A + (size_t)(m0 + a_row)      * K + a_c4;
    const float* gB0 = B + (size_t)(n0 + a_row)      * K + a_c4;
    const float* gB1 = B + (size_t)(n0 + 64 + a_row) * K + a_c4;
    unsigned s_a[2], s_b0[2], s_b1[2];
    #pragma unroll
    for (int bb = 0; bb < 2; ++bb) {
        s_a [bb] = (unsigned)__cvta_generic_to_shared(&sA[bb][a_row][a_c4]);
        s_b0[bb] = (unsigned)__cvta_generic_to_shared(&sB[bb][a_row][a_c4]);
        s_b1[bb] = (unsigned)__cvta_generic_to_shared(&sB[bb][64 + a_row][a_c4]);
    }

    float acc[2][4][4];
    #pragma unroll
    for (int i = 0; i < 2; ++i)
        #pragma unroll
        for (int j = 0; j < 4; ++j)
            #pragma unroll
            for (int k = 0; k < 4; ++k) acc[i][j][k] = 0.f;

    const int nk = K >> 4;
    // stage tile 0
    cp16(s_a[0], gA); cp16(s_b0[0], gB0); cp16(s_b1[0], gB1); cp_commit();

    for (int kt = 0; kt < nk; ++kt) {
        if (kt + 1 < nk) {
            int k0 = (kt + 1) << 4, nb = (kt + 1) & 1;
            cp16(s_a[nb], gA + k0); cp16(s_b0[nb], gB0 + k0); cp16(s_b1[nb], gB1 + k0);
            cp_commit();
            cp_wait<1>();
        } else {
            cp_wait<0>();
        }
        __syncthreads();
        const int buf = kt & 1;
        #pragma unroll
        for (int ks = 0; ks < 16; ks += 8) {
            const int ac = ks + (lane & 3);
            const int ar = wm * 32 + (lane >> 2);
            unsigned af[2][4];
            #pragma unroll
            for (int mf = 0; mf < 2; ++mf) {
                af[mf][0] = f2tf32(sA[buf][ar + mf*16    ][ac    ]);
                af[mf][1] = f2tf32(sA[buf][ar + mf*16 + 8][ac    ]);
                af[mf][2] = f2tf32(sA[buf][ar + mf*16    ][ac + 4]);
                af[mf][3] = f2tf32(sA[buf][ar + mf*16 + 8][ac + 4]);
            }
            const int br = wn * 32 + (lane >> 2);
            unsigned bf[4][2];
            #pragma unroll
            for (int nf = 0; nf < 4; ++nf) {
                bf[nf][0] = f2tf32(sB[buf][br + nf*8][ac    ]);
                bf[nf][1] = f2tf32(sB[buf][br + nf*8][ac + 4]);
            }
            #pragma unroll
            for (int mf = 0; mf < 2; ++mf)
                #pragma unroll
                for (int nf = 0; nf < 4; ++nf)
                    mma_tf32(acc[mf][nf], af[mf], bf[nf]);
        }
        __syncthreads();
    }

    // epilogue
    #pragma unroll
    for (int mf = 0; mf < 2; ++mf) {
        #pragma unroll
        for (int nf = 0; nf < 4; ++nf) {
            int row = m0 + wm * 32 + mf * 16 + (lane >> 2);
            int col = n0 + wn * 32 + nf * 8 + (lane & 3) * 2;
            float s0 = scale ? scale[col]     : 1.f;
            float s1 = scale ? scale[col + 1] : 1.f;
            float b0 = bias  ? bias[col]      : 0.f;
            float b1 = bias  ? bias[col + 1]  : 0.f;
            #pragma unroll
            for (int half = 0; half < 2; ++half) {
                int r = row + half * 8;
                float2 v;
                v.x = acc[mf][nf][half*2 + 0] * s0 + b0;
                v.y = acc[mf][nf][half*2 + 1] * s1 + b1;
                size_t idx;
                if (remap) { int b_ = r & 63, t_ = r >> 6; idx = ((size_t)(b_ * TT + t_)) * N + col; }
                else       { idx = (size_t)r * N + col; }
                *(float2*)(C + idx) = v;
            }
        }
    }
}

// ---------------------------------------------------------------- fused GRU step
// gh = h_prev @ W_hh^T (+ b_hh), then cell update -> HS[t]
// Block: 16 hidden units, 384 threads = 12 warps: gate = w%3, kq = w/3 (K quarter of 256)
struct GruAB { float A[4][64][20]; float B[4][3][16][20]; };
union GruSmem { GruAB ab; float GH[3][64][16]; };

__global__ __launch_bounds__(384) void gru_step_kernel(
    const float* __restrict__ Whh, const float* __restrict__ bhh, int t) {
    __shared__ GruSmem sm;
    const int tid = threadIdx.x, lane = tid & 31, warp = tid >> 5;
    const int gate = warp % 3, kq = warp / 3;
    const int j0 = blockIdx.x * 16;
    const float* hprev = (t == 0) ? nullptr : (d_HS + (size_t)(t - 1) * BB * GG);

    float acc[4][2][4];
    #pragma unroll
    for (int i = 0; i < 4; ++i)
        #pragma unroll
        for (int j = 0; j < 2; ++j)
            #pragma unroll
            for (int k = 0; k < 4; ++k) acc[i][j][k] = 0.f;

    if (hprev) {
        for (int kt = 0; kt < 16; ++kt) {
            // stage A: 4 quarters x 64 rows x 4 float4 = 1024 f4
            for (int idx = tid; idx < 1024; idx += 384) {
                int q = idx >> 8, rem = idx & 255;
                int row = rem >> 2, c4 = (rem & 3) * 4;
                float4 v = *(const float4*)(hprev + (size_t)row * GG + q * 256 + kt * 16 + c4);
                *(float4*)(&sm.ab.A[q][row][c4]) = v;
            }
            // stage B: 4 quarters x 3 gates x 16 rows x 4 f4 = 768 f4
            for (int idx = tid; idx < 768; idx += 384) {
                int q = idx / 192, rem = idx % 192;
                int g = rem / 64, r2 = rem % 64;
                int row = r2 >> 2, c4 = (r2 & 3) * 4;
                float4 v = *(const float4*)(Whh + (size_t)(g * GG + j0 + row) * GG + q * 256 + kt * 16 + c4);
                *(float4*)(&sm.ab.B[q][g][row][c4]) = v;
            }
            __syncthreads();
            #pragma unroll
            for (int ks = 0; ks < 16; ks += 8) {
                const int ac = ks + (lane & 3);
                const int arb = lane >> 2;
                unsigned af[4][4];
                #pragma unroll
                for (int mf = 0; mf < 4; ++mf) {
                    af[mf][0] = f2tf32(sm.ab.A[kq][mf*16 + arb    ][ac    ]);
                    af[mf][1] = f2tf32(sm.ab.A[kq][mf*16 + arb + 8][ac    ]);
                    af[mf][2] = f2tf32(sm.ab.A[kq][mf*16 + arb    ][ac + 4]);
                    af[mf][3] = f2tf32(sm.ab.A[kq][mf*16 + arb + 8][ac + 4]);
                }
                unsigned bfr[2][2];
                #pragma unroll
                for (int nf = 0; nf < 2; ++nf) {
                    bfr[nf][0] = f2tf32(sm.ab.B[kq][gate][nf*8 + arb][ac    ]);
                    bfr[nf][1] = f2tf32(sm.ab.B[kq][gate][nf*8 + arb][ac + 4]);
                }
                #pragma unroll
                for (int mf = 0; mf < 4; ++mf)
                    #pragma unroll
                    for (int nf = 0; nf < 2; ++nf)
                        mma_tf32(acc[mf][nf], af[mf], bfr[nf]);
            }
            __syncthreads();
        }
    }

    // reduce the 4 K-quarters into smem GH[gate][m][n]
    float* GHf = &sm.GH[0][0][0];
    for (int idx = tid; idx < 3 * 64 * 16; idx += 384) GHf[idx] = 0.f;
    __syncthreads();
    #pragma unroll 1
    for (int q = 0; q < 4; ++q) {
        if (kq == q) {
            #pragma unroll
            for (int mf = 0; mf < 4; ++mf)
                #pragma unroll
                for (int nf = 0; nf < 2; ++nf)
                    #pragma unroll
                    for (int ci = 0; ci < 4; ++ci) {
                        int m = mf * 16 + (lane >> 2) + ((ci >= 2) ? 8 : 0);
                        int n = nf * 8 + (lane & 3) * 2 + (ci & 1);
                        sm.GH[gate][m][n] += acc[mf][nf][ci];
                    }
        }
        __syncthreads();
    }

    // cell update
    for (int idx = tid; idx < 64 * 16; idx += 384) {
        int m = idx >> 4, n = idx & 15;
        int j = j0 + n;
        float ghr = sm.GH[0][m][n] + bhh[j];
        float ghz = sm.GH[1][m][n] + bhh[GG + j];
        float ghn = sm.GH[2][m][n] + bhh[2 * GG + j];
        const float* gi = d_GI + ((size_t)t * BB + m) * (3 * GG);
        float r  = sigmoidf_fast(gi[j]          + ghr);
        float z  = sigmoidf_fast(gi[GG + j]     + ghz);
        float nn = tanhf        (gi[2*GG + j]   + r * ghn);
        float hp = hprev ? hprev[(size_t)m * GG + j] : 0.f;
        float hn = (1.f - z) * nn + z * hp;
        d_HS[((size_t)t * BB + m) * GG + j] = hn;
    }
}

// ---------------------------------------------------------------- launch
extern "C" void kernel_launch(void* const* d_in, const int* in_sizes, int n_in,
                              void* d_out, int out_size) {
    const float* features = (const float*)d_in[0];
    const int*   input_ids= (const int*)  d_in[1];
    const float* emb      = (const float*)d_in[2];
    const float* img_v    = (const float*)d_in[3];
    const float* img_g    = (const float*)d_in[4];
    const float* img_b    = (const float*)d_in[5];
    const float* W_ih     = (const float*)d_in[6];
    const float* W_hh     = (const float*)d_in[7];
    const float* b_ih     = (const float*)d_in[8];
    const float* b_hh     = (const float*)d_in[9];
    const float* fc_v     = (const float*)d_in[10];
    const float* fc_g     = (const float*)d_in[11];
    const float* fc_b     = (const float*)d_in[12];
    float* out = (float*)d_out;

    float *dX, *dGI, *dHS, *dSI, *dSF;
    cudaGetSymbolAddress((void**)&dX,  d_X);
    cudaGetSymbolAddress((void**)&dGI, d_GI);
    cudaGetSymbolAddress((void**)&dHS, d_HS);
    cudaGetSymbolAddress((void**)&dSI, d_scale_img);
    cudaGetSymbolAddress((void**)&dSF, d_scale_fc);

    // weight-norm scales
    rownorm_kernel<<<EE, 128>>>(img_v, img_g, dSI, FF);
    rownorm_kernel<<<VV, 128>>>(fc_v, fc_g, dSF, GG);

    // build X: t=0 from img embed, t>=1 embedding gather
    gather_kernel<<<(TT - 1) * BB, 128>>>(input_ids, emb);
    img_embed_kernel<<<(BB * EE) / 8, 256>>>(features, img_v, dSI, img_b);

    // GI = X @ W_ih^T + b_ih   (M=1280, N=3072, K=512)
    {
        dim3 grid(MROWS / 64, (3 * GG) / 128);
        gemm_tf32_kernel<<<grid, 256>>>(dX, W_ih, dGI, nullptr, b_ih,
                                        MROWS, 3 * GG, EE, 0);
    }

    // GRU recurrence
    for (int t = 0; t < TT; ++t)
        gru_step_kernel<<<GG / 16, 384>>>(W_hh, b_hh, t);

    // FC: out[b,t,:] = HS[t,b,:] @ (scale*fc_v)^T + fc_b   (M=1280, N=32000, K=1024)
    {
        dim3 grid(MROWS / 64, VV / 128);
        gemm_tf32_kernel<<<grid, 256>>>(dHS, fc_v, out, dSF, fc_b,
                                        MROWS, VV, GG, 1);
    }
    (void)in_sizes; (void)n_in; (void)out_size;
}

// round 2
// speedup vs baseline: 2.3056x; 2.3056x over previous
#include <cuda_runtime.h>
#include <cuda_fp16.h>
#include <math.h>
#include <stdint.h>

// Problem dims (fixed)
#define BB   64
#define TT   20
#define FF   2048
#define EE   512
#define GG   1024
#define VV   32000
#define MROWS (BB*TT)   // 1280

// Scratch (device globals; no allocation allowed)
__device__ float  d_GI [MROWS * 3 * GG];   // [t*B + b][3G] precomputed input gates (fp32)
__device__ float  d_HS [MROWS * GG];       // hidden states fp32 (recurrence-exact)
__device__ __half d_HSh[MROWS * GG];       // hidden states fp16 (MMA input)
__device__ __half d_Xh [MROWS * EE];       // input sequence fp16, time-major
__device__ __half d_feat_h[BB * FF];
__device__ __half d_Wih_h [3 * GG * EE];
__device__ __half d_Whh_h [3 * GG * GG];
__device__ __half d_imgv_h[EE * FF];       // weight-norm scale folded in
__device__ __half d_fcv_h [VV * GG];       // weight-norm scale folded in

// ---------------------------------------------------------------- helpers
__device__ __forceinline__ void mma_f16(float c[4], const unsigned a[4], const unsigned b[2]) {
    asm volatile(
      "mma.sync.aligned.m16n8k16.row.col.f32.f16.f16.f32 "
      "{%0,%1,%2,%3},{%4,%5,%6,%7},{%8,%9},{%0,%1,%2,%3};\n"
      : "+f"(c[0]), "+f"(c[1]), "+f"(c[2]), "+f"(c[3])
      : "r"(a[0]), "r"(a[1]), "r"(a[2]), "r"(a[3]), "r"(b[0]), "r"(b[1]));
}
__device__ __forceinline__ void ldm_x4(unsigned& r0, unsigned& r1, unsigned& r2, unsigned& r3,
                                       const __half* p) {
    unsigned a = (unsigned)__cvta_generic_to_shared(p);
    asm volatile("ldmatrix.sync.aligned.m8n8.x4.shared.b16 {%0,%1,%2,%3}, [%4];"
                 : "=r"(r0), "=r"(r1), "=r"(r2), "=r"(r3) : "r"(a));
}
__device__ __forceinline__ void ldm_x2(unsigned& r0, unsigned& r1, const __half* p) {
    unsigned a = (unsigned)__cvta_generic_to_shared(p);
    asm volatile("ldmatrix.sync.aligned.m8n8.x2.shared.b16 {%0,%1}, [%2];"
                 : "=r"(r0), "=r"(r1) : "r"(a));
}
__device__ __forceinline__ void cp16(unsigned dst, const void* src) {
    asm volatile("cp.async.cg.shared.global [%0], [%1], 16;\n" :: "r"(dst), "l"(src));
}
__device__ __forceinline__ void cp_commit() {
    asm volatile("cp.async.commit_group;\n" ::: "memory");
}
template<int N> __device__ __forceinline__ void cp_wait() {
    asm volatile("cp.async.wait_group %0;\n" :: "n"(N) : "memory");
}
__device__ __forceinline__ float sigmoidf_fast(float x) {
    return 1.0f / (1.0f + __expf(-x));
}
// XOR-swizzled layout for a [rows][32-half] tile stored as [rows/2][64-half] physical rows.
// Conflict-free for ldmatrix (8-row loads) and 16B STS. Returns half-offset; k in [0,32).
__device__ __forceinline__ int swz(int row, int k) {
    int c = k >> 3;
    return ((row >> 1) << 6) + ((((((row & 1) << 2) | c)) ^ ((row >> 1) & 7)) << 3) + (k & 7);
}

// ---------------------------------------------------------------- conversions
__global__ void f2h_kernel(const float* __restrict__ src, __half* __restrict__ dst, int n) {
    int i = (blockIdx.x * blockDim.x + threadIdx.x) * 4;
    if (i < n) {
        float4 v = *(const float4*)(src + i);
        __half2* d = (__half2*)(dst + i);
        d[0] = __floats2half2_rn(v.x, v.y);
        d[1] = __floats2half2_rn(v.z, v.w);
    }
}

// weight-norm fold + convert: out[row][:] = fp16( V[row][:] * g[row] / ||V[row]|| )
__global__ void wn_convert_kernel(const float* __restrict__ V, const float* __restrict__ g,
                                  __half* __restrict__ out, int K) {
    int row = blockIdx.x, tid = threadIdx.x;
    const float4* v = (const float4*)(V + (size_t)row * K);
    int n4 = K >> 2;
    float s = 0.f;
    for (int i = tid; i < n4; i += blockDim.x) {
        float4 x = v[i];
        s += x.x*x.x + x.y*x.y + x.z*x.z + x.w*x.w;
    }
    for (int o = 16; o; o >>= 1) s += __shfl_xor_sync(0xffffffffu, s, o);
    __shared__ float red[4];
    __shared__ float scs;
    if ((tid & 31) == 0) red[tid >> 5] = s;
    __syncthreads();
    if (tid == 0) scs = g[row] / sqrtf(red[0] + red[1] + red[2] + red[3]);
    __syncthreads();
    float sc = scs;
    __half2* o2 = (__half2*)(out + (size_t)row * K);
    for (int i = tid; i < n4; i += blockDim.x) {
        float4 x = v[i];
        o2[2*i]   = __floats2half2_rn(x.x * sc, x.y * sc);
        o2[2*i+1] = __floats2half2_rn(x.z * sc, x.w * sc);
    }
}

// embedding gather -> fp16 X rows for t>=1
__global__ void gather_h_kernel(const int* __restrict__ ids, const float* __restrict__ emb) {
    int t = blockIdx.x / BB + 1;
    int b = blockIdx.x % BB;
    int id = ids[b * TT + t];
    const float4* src = (const float4*)(emb + (size_t)id * EE);
    __half2* dst = (__half2*)(d_Xh + ((size_t)t * BB + b) * EE);
    for (int i = threadIdx.x; i < EE / 4; i += blockDim.x) {
        float4 v = src[i];
        dst[2*i]   = __floats2half2_rn(v.x, v.y);
        dst[2*i+1] = __floats2half2_rn(v.z, v.w);
    }
}

// ---------------------------------------------------------------- fp16 GEMM
// C[m,n] = sum_k A[m,k]*B[n,k] + bias[n]
// BM=128 BN=128 BK=32, 256 threads (8 warps 2x4), warp tile 64x32, cp.async double buffer.
// REMAP: row m = t*64+b -> write C[(b*TT+t)*N + n]. OUTHALF: C is __half.
template<int REMAP, int OUTHALF>
__global__ __launch_bounds__(256) void gemm_f16_kernel(
    const __half* __restrict__ A, const __half* __restrict__ B, void* __restrict__ Cv,
    const float* __restrict__ bias, int Mreal, int N, int K) {
    __shared__ __half sA[2][128 * 32];
    __shared__ __half sB[2][128 * 32];

    const int tid = threadIdx.x, lane = tid & 31, warp = tid >> 5;
    const int wm = warp >> 2, wn = warp & 3;
    const int m0 = blockIdx.x * 128, n0 = blockIdx.y * 128;

    float acc[4][4][4];
    #pragma unroll
    for (int i = 0; i < 4; ++i)
        #pragma unroll
        for (int j = 0; j < 4; ++j)
            #pragma unroll
            for (int k = 0; k < 4; ++k) acc[i][j][k] = 0.f;

    const int nk = K >> 5;

    auto stage = [&](int kt, int buf) {
        int kofs = kt * 32;
        #pragma unroll
        for (int j = 0; j < 2; ++j) {
            int idx = tid + j * 256;
            int row = idx >> 2, ch = (idx & 3) * 8;
            int arow = m0 + row; if (arow >= Mreal) arow = Mreal - 1;
            cp16((unsigned)__cvta_generic_to_shared(&sA[buf][swz(row, ch)]),
                 A + (size_t)arow * K + kofs + ch);
            cp16((unsigned)__cvta_generic_to_shared(&sB[buf][swz(row, ch)]),
                 B + (size_t)(n0 + row) * K + kofs + ch);
        }
    };

    stage(0, 0); cp_commit();

    for (int kt = 0; kt < nk; ++kt) {
        __syncthreads();   // prior reads of the buffer we are about to overwrite are done
        if (kt + 1 < nk) { stage(kt + 1, (kt + 1) & 1); cp_commit(); cp_wait<1>(); }
        else             { cp_wait<0>(); }
        __syncthreads();   // staged data visible to all
        const int buf = kt & 1;
        #pragma unroll
        for (int ks = 0; ks < 32; ks += 16) {
            unsigned af[4][4];
            #pragma unroll
            for (int mf = 0; mf < 4; ++mf) {
                int row = wm * 64 + mf * 16 + (lane & 15);
                ldm_x4(af[mf][0], af[mf][1], af[mf][2], af[mf][3],
                       &sA[buf][swz(row, ks + ((lane >> 4) << 3))]);
            }
            unsigned bf[4][2];
            #pragma unroll
            for (int nf2 = 0; nf2 < 2; ++nf2) {
                int g = lane >> 3;
                int row = wn * 32 + nf2 * 16 + ((g >> 1) << 3) + (lane & 7);
                unsigned t0, t1, t2, t3;
                ldm_x4(t0, t1, t2, t3, &sB[buf][swz(row, ks + ((g & 1) << 3))]);
                bf[nf2*2][0] = t0; bf[nf2*2][1] = t1;
                bf[nf2*2+1][0] = t2; bf[nf2*2+1][1] = t3;
            }
            #pragma unroll
            for (int mf = 0; mf < 4; ++mf)
                #pragma unroll
                for (int nf = 0; nf < 4; ++nf)
                    mma_f16(acc[mf][nf], af[mf], bf[nf]);
        }
    }

    // epilogue
    #pragma unroll
    for (int mf = 0; mf < 4; ++mf) {
        #pragma unroll
        for (int nf = 0; nf < 4; ++nf) {
            int row = m0 + wm * 64 + mf * 16 + (lane >> 2);
            int col = n0 + wn * 32 + nf * 8 + (lane & 3) * 2;
            float b0 = bias ? bias[col]     : 0.f;
            float b1 = bias ? bias[col + 1] : 0.f;
            #pragma unroll
            for (int half = 0; half < 2; ++half) {
                int r = row + half * 8;
                if (r >= Mreal) continue;
                float v0 = acc[mf][nf][half*2 + 0] + b0;
                float v1 = acc[mf][nf][half*2 + 1] + b1;
                size_t idx;
                if (REMAP) { int b_ = r & 63, t_ = r >> 6; idx = ((size_t)(b_ * TT + t_)) * N + col; }
                else       { idx = (size_t)r * N + col; }
                if (OUTHALF) *(__half2*)((__half*)Cv + idx) = __floats2half2_rn(v0, v1);
                else         *(float2*)((float*)Cv + idx)   = make_float2(v0, v1);
            }
        }
    }
}

// ---------------------------------------------------------------- fused GRU step
// gh = h_prev @ W_hh^T (+ b_hh), then cell update -> HS[t] (fp32 + fp16 copies)
// 128 blocks x 8 hidden cols; 384 threads = 12 warps: gate = w%3, K-quarter = w/3.
__global__ __launch_bounds__(384) void gru_step_kernel(
    const __half* __restrict__ Whh, const float* __restrict__ bhh, int t) {
    __shared__ union {
        struct { __half A[4][64 * 32]; __half Bw[4][3][8 * 32]; } s;  // swizzled tiles
        float GH[3][64][8];
    } sm;
    const int tid = threadIdx.x, lane = tid & 31, warp = tid >> 5;
    const int gate = warp % 3, kq = warp / 3;
    const int j0 = blockIdx.x * 8;
    const __half* hprev = (t == 0) ? nullptr : (d_HSh + (size_t)(t - 1) * BB * GG);

    float acc[4][4];
    #pragma unroll
    for (int i = 0; i < 4; ++i)
        #pragma unroll
        for (int j = 0; j < 4; ++j) acc[i][j] = 0.f;

    if (hprev) {
        for (int kt = 0; kt < 8; ++kt) {
            __syncthreads();
            // stage A: 4 quarters x 64 rows x 4 chunks of 8 halfs = 1024 chunks
            for (int idx = tid; idx < 1024; idx += 384) {
                int q = idx >> 8, rem = idx & 255, row = rem >> 2, c = (rem & 3) * 8;
                *(uint4*)&sm.s.A[q][swz(row, c)] =
                    *(const uint4*)(hprev + (size_t)row * GG + q * 256 + kt * 32 + c);
            }
            // stage B: 4 x 3 x 8 x 4 = 384 chunks (exactly one per thread)
            {
                int idx = tid;
                int q = idx / 96, rem = idx % 96, g = rem / 32, r2 = rem % 32;
                int n = r2 >> 2, c = (r2 & 3) * 8;
                *(uint4*)&sm.s.Bw[q][g][swz(n, c)] =
                    *(const uint4*)(Whh + (size_t)(g * GG + j0 + n) * GG + q * 256 + kt * 32 + c);
            }
            __syncthreads();
            #pragma unroll
            for (int ks = 0; ks < 32; ks += 16) {
                unsigned af[4][4];
                #pragma unroll
                for (int mf = 0; mf < 4; ++mf) {
                    int row = mf * 16 + (lane & 15);
                    ldm_x4(af[mf][0], af[mf][1], af[mf][2], af[mf][3],
                           &sm.s.A[kq][swz(row, ks + ((lane >> 4) << 3))]);
                }
                unsigned bf[2];
                ldm_x2(bf[0], bf[1],
                       &sm.s.Bw[kq][gate][swz(lane & 7, ks + (lane & 8))]);
                #pragma unroll
                for (int mf = 0; mf < 4; ++mf) mma_f16(acc[mf], af[mf], bf);
            }
        }
    }

    __syncthreads();
    // reduce the 4 K-quarters into GH[gate][m][n]
    float* GHf = &sm.GH[0][0][0];
    for (int i = tid; i < 3 * 64 * 8; i += 384) GHf[i] = 0.f;
    __syncthreads();
    #pragma unroll 1
    for (int q = 0; q < 4; ++q) {
        if (kq == q) {
            #pragma unroll
            for (int mf = 0; mf < 4; ++mf)
                #pragma unroll
                for (int ci = 0; ci < 4; ++ci) {
                    int m = mf * 16 + (lane >> 2) + ((ci >= 2) ? 8 : 0);
                    int n = (lane & 3) * 2 + (ci & 1);
                    sm.GH[gate][m][n] += acc[mf][ci];
                }
        }
        __syncthreads();
    }

    // cell update
    const float* hp32 = (t == 0) ? nullptr : (d_HS + (size_t)(t - 1) * BB * GG);
    for (int idx = tid; idx < 64 * 8; idx += 384) {
        int m = idx >> 3, n = idx & 7;
        int j = j0 + n;
        float ghr = sm.GH[0][m][n] + bhh[j];
        float ghz = sm.GH[1][m][n] + bhh[GG + j];
        float ghn = sm.GH[2][m][n] + bhh[2 * GG + j];
        const float* gi = d_GI + ((size_t)t * BB + m) * (3 * GG);
        float r  = sigmoidf_fast(gi[j]        + ghr);
        float z  = sigmoidf_fast(gi[GG + j]   + ghz);
        float nn = tanhf        (gi[2*GG + j] + r * ghn);
        float hp = hp32 ? hp32[(size_t)m * GG + j] : 0.f;
        float hn = (1.f - z) * nn + z * hp;
        d_HS [((size_t)t * BB + m) * GG + j] = hn;
        d_HSh[((size_t)t * BB + m) * GG + j] = __float2half_rn(hn);
    }
}

// ---------------------------------------------------------------- launch
extern "C" void kernel_launch(void* const* d_in, const int* in_sizes, int n_in,
                              void* d_out, int out_size) {
    const float* features = (const float*)d_in[0];
    const int*   input_ids= (const int*)  d_in[1];
    const float* emb      = (const float*)d_in[2];
    const float* img_v    = (const float*)d_in[3];
    const float* img_g    = (const float*)d_in[4];
    const float* img_b    = (const float*)d_in[5];
    const float* W_ih     = (const float*)d_in[6];
    const float* W_hh     = (const float*)d_in[7];
    const float* b_ih     = (const float*)d_in[8];
    const float* b_hh     = (const float*)d_in[9];
    const float* fc_v     = (const float*)d_in[10];
    const float* fc_g     = (const float*)d_in[11];
    const float* fc_b     = (const float*)d_in[12];
    float* out = (float*)d_out;

    float *dGI;  __half *dHSh, *dXh, *dFeat, *dWih, *dWhh, *dImgv, *dFcv;
    cudaGetSymbolAddress((void**)&dGI,  d_GI);
    cudaGetSymbolAddress((void**)&dHSh, d_HSh);
    cudaGetSymbolAddress((void**)&dXh,  d_Xh);
    cudaGetSymbolAddress((void**)&dFeat,d_feat_h);
    cudaGetSymbolAddress((void**)&dWih, d_Wih_h);
    cudaGetSymbolAddress((void**)&dWhh, d_Whh_h);
    cudaGetSymbolAddress((void**)&dImgv,d_imgv_h);
    cudaGetSymbolAddress((void**)&dFcv, d_fcv_h);

    // weight conversions (once per call; cheap memory passes)
    f2h_kernel<<<(BB*FF/4 + 255)/256, 256>>>(features, dFeat, BB*FF);
    f2h_kernel<<<(3*GG*EE/4 + 255)/256, 256>>>(W_ih, dWih, 3*GG*EE);
    f2h_kernel<<<(3*GG*GG/4 + 255)/256, 256>>>(W_hh, dWhh, 3*GG*GG);
    wn_convert_kernel<<<EE, 128>>>(img_v, img_g, dImgv, FF);
    wn_convert_kernel<<<VV, 128>>>(fc_v, fc_g, dFcv, GG);

    // build X: t>=1 embedding gather (fp16), t=0 img embed via GEMM
    gather_h_kernel<<<(TT - 1) * BB, 128>>>(input_ids, emb);
    {
        dim3 grid(1, EE / 128);   // M=64 (clamped/guarded), N=512, K=2048
        gemm_f16_kernel<0,1><<<grid, 256>>>(dFeat, dImgv, dXh, img_b, BB, EE, FF);
    }

    // GI = X @ W_ih^T + b_ih   (M=1280, N=3072, K=512)
    {
        dim3 grid(MROWS / 128, (3 * GG) / 128);
        gemm_f16_kernel<0,0><<<grid, 256>>>(dXh, dWih, dGI, b_ih, MROWS, 3 * GG, EE);
    }

    // GRU recurrence (20 sequential steps)
    for (int t = 0; t < TT; ++t)
        gru_step_kernel<<<GG / 8, 384>>>(dWhh, b_hh, t);

    // FC: out[b,t,:] = HS[t,b,:] @ fc_wn^T + fc_b   (M=1280, N=32000, K=1024)
    {
        dim3 grid(MROWS / 128, VV / 128);
        gemm_f16_kernel<1,0><<<grid, 256>>>(dHSh, dFcv, out, fc_b, MROWS, VV, GG);
    }
    (void)in_sizes; (void)n_in; (void)out_size;
}